// round 4
// baseline (speedup 1.0000x reference)
#include <cuda_runtime.h>
#include <cuda_fp16.h>
#include <mma.h>

using namespace nvcuda;

// Problem constants
#define NMSB 4
#define BB   256            // batch
#define IND  1024           // input dim (= K)
#define H4   4096           // 4*H
#define NTOT 8192           // ih(4096) ++ hh(4096)

// GEMM tiling
#define BM 128
#define BN 64
#define BK 32

// -------- static device scratch (no dynamic allocation allowed) --------
__device__ float  g_max[4];                       // max(wih), max(whh), max(bih), max(bhh)
__device__ __half g_x[NMSB * BB * IND];           // bit-planes as fp16 {0,1}
__device__ float  g_C[(size_t)NMSB * BB * NTOT];  // raw matmul outputs (pre-bias)

// -------- exact replicas of reference elementwise ops --------
__device__ __forceinline__ float pact_a_f(float x, float a) {
    float sg = (x > 0.f) ? 1.f : ((x < 0.f) ? -1.f : 0.f);
    float ax = fabsf(x);
    return (sg * 0.5f) * ((ax - fabsf(ax - a)) + a);
}

// _quant_val(x, 8, a): step=128
__device__ __forceinline__ float quant8(float x, float a) {
    float x01 = x / a;
    x01 = fminf(fmaxf(x01, -0.9921875f), 0.9921875f);
    return (rintf(x01 * 128.f) * 0.0078125f) * a;
}

// weight quantization (range 1.0) + noise, replicating:
//   w + ((quant(w) - w) + (eps*max)*0.1)
__device__ __forceinline__ float w_eff_f(float w, float eps, float maxw) {
    float c = fminf(fmaxf(w, -0.9921875f), 0.9921875f);
    float q = rintf(c * 128.f) * 0.0078125f;
    return w + ((q - w) + (eps * maxw) * 0.1f);
}

// XLA-style logistic via tanh
__device__ __forceinline__ float sig_f(float x) {
    return 0.5f * tanhf(0.5f * x) + 0.5f;
}

// ---------------- phase 0a: init maxima ----------------
__global__ void k_init() {
    if (threadIdx.x < 4) g_max[threadIdx.x] = -INFINITY;
}

// ---------------- phase 0b: global max reduction ----------------
__global__ void k_max(const float* __restrict__ p, int nelem, int slot) {
    float m = -INFINITY;
    for (int i = blockIdx.x * blockDim.x + threadIdx.x; i < nelem;
         i += gridDim.x * blockDim.x)
        m = fmaxf(m, p[i]);
    #pragma unroll
    for (int o = 16; o; o >>= 1) m = fmaxf(m, __shfl_xor_sync(0xFFFFFFFFu, m, o));
    __shared__ float sm[8];
    if ((threadIdx.x & 31) == 0) sm[threadIdx.x >> 5] = m;
    __syncthreads();
    if (threadIdx.x < 32) {
        float v = (threadIdx.x < (blockDim.x >> 5)) ? sm[threadIdx.x] : -INFINITY;
        #pragma unroll
        for (int o = 16; o; o >>= 1) v = fmaxf(v, __shfl_xor_sync(0xFFFFFFFFu, v, o));
        if (threadIdx.x == 0) {
            if (v >= 0.f) atomicMax((int*)&g_max[slot], __float_as_int(v));
            else          atomicMin((unsigned int*)&g_max[slot], __float_as_uint(v));
        }
    }
}

// ---------------- phase 0c: bit planes (exact fp32 replica) ----------------
__global__ void k_bits(const float* __restrict__ input, const float* __restrict__ a1p) {
    int idx = blockIdx.x * blockDim.x + threadIdx.x;  // < BB*IND
    float a = a1p[0];
    float x = input[idx];
    float pact  = pact_a_f(x, a);
    float inp01 = (pact + a) / (a * 2.0f);
    float r  = rintf(15.0f * inp01);    // l1 = 2^4 - 1
    int   ri = (int)r;                  // in [0,15]
    #pragma unroll
    for (int n = 0; n < NMSB; n++) {
        int bit = (ri >> (3 - n)) & 1;  // l2 = 8,4,2,1 => MSB-first bits
        g_x[n * (BB * IND) + idx] = __float2half_rn(bit ? 1.f : 0.f);
    }
}

// ---------------- phase 1: fp16 2-limb tensor-core GEMM ----------------
// C[n][256][8192] = x[n] (256x1024, binary) @ Wcat_eff[n] (1024x8192)
// Each fp32 effective weight is split into hi+lo fp16 limbs; since A is
// binary the products are exact, and fp32 MMA accumulation reproduces
// fp32 GEMM semantics up to reordering noise.
__global__ void __launch_bounds__(256)
k_gemm(const float* __restrict__ wih, const float* __restrict__ whh,
       const float* __restrict__ ewih, const float* __restrict__ ewhh) {
    __shared__ __half As[BM][BK + 8];
    __shared__ __half Bh[BK][BN + 8];
    __shared__ __half Bl[BK][BN + 8];

    const int n       = blockIdx.z;
    const int m_base  = blockIdx.y * BM;
    const int nn_base = blockIdx.x * BN;
    const int set     = (nn_base >= H4) ? 1 : 0;
    const float* W = set ? whh : wih;
    const float* E = set ? ewhh : ewih;
    const float maxw = g_max[set];
    const int o_base = nn_base & (H4 - 1);

    const __half* X  = g_x + (size_t)n * BB * IND;
    const float*  Wn = W + (size_t)n * IND * H4;
    const float*  En = E + (size_t)n * IND * H4;

    const int tid  = threadIdx.x;
    const int warp = tid >> 5;
    const int wm   = warp >> 1;   // 0..3 (M dir)
    const int wn   = warp & 1;    // 0..1 (N dir)

    wmma::fragment<wmma::accumulator, 16, 16, 16, float> acc[2][2];
    #pragma unroll
    for (int i = 0; i < 2; i++)
        #pragma unroll
        for (int j = 0; j < 2; j++) wmma::fill_fragment(acc[i][j], 0.f);

    const int arow = tid >> 1;          // A: 128 rows x (2 groups of 16 cols)
    const int acg  = (tid & 1) * 16;
    const int brow = tid >> 3;          // B: 32 rows x (8 cols per thread)
    const int bcol = (tid & 7) * 8;

    for (int k0 = 0; k0 < IND; k0 += BK) {
        // A tile: 128x32 fp16
        const __half* ga = X + (size_t)(m_base + arow) * IND + k0 + acg;
        *(float4*)&As[arow][acg]     = *(const float4*)ga;
        *(float4*)&As[arow][acg + 8] = *(const float4*)(ga + 8);

        // B tile: 32x64, compute w_eff and split into hi/lo fp16
        const float* gw = Wn + (size_t)(k0 + brow) * H4 + o_base + bcol;
        const float* ge = En + (size_t)(k0 + brow) * H4 + o_base + bcol;
        float4 w0 = *(const float4*)gw, w1 = *(const float4*)(gw + 4);
        float4 e0 = *(const float4*)ge, e1 = *(const float4*)(ge + 4);
        float wv[8] = {w0.x, w0.y, w0.z, w0.w, w1.x, w1.y, w1.z, w1.w};
        float ev[8] = {e0.x, e0.y, e0.z, e0.w, e1.x, e1.y, e1.z, e1.w};
        #pragma unroll
        for (int u = 0; u < 8; u++) {
            float weff = w_eff_f(wv[u], ev[u], maxw);
            __half hi = __float2half_rn(weff);
            float  lo = weff - __half2float(hi);
            Bh[brow][bcol + u] = hi;
            Bl[brow][bcol + u] = __float2half_rn(lo);
        }
        __syncthreads();

        #pragma unroll
        for (int kk = 0; kk < BK; kk += 16) {
            wmma::fragment<wmma::matrix_a, 16, 16, 16, __half, wmma::row_major> af[2];
            wmma::fragment<wmma::matrix_b, 16, 16, 16, __half, wmma::row_major> bf;
            #pragma unroll
            for (int i = 0; i < 2; i++)
                wmma::load_matrix_sync(af[i], &As[wm * 32 + i * 16][kk], BK + 8);
            #pragma unroll
            for (int j = 0; j < 2; j++) {
                wmma::load_matrix_sync(bf, &Bh[kk][wn * 32 + j * 16], BN + 8);
                #pragma unroll
                for (int i = 0; i < 2; i++) wmma::mma_sync(acc[i][j], af[i], bf, acc[i][j]);
                wmma::load_matrix_sync(bf, &Bl[kk][wn * 32 + j * 16], BN + 8);
                #pragma unroll
                for (int i = 0; i < 2; i++) wmma::mma_sync(acc[i][j], af[i], bf, acc[i][j]);
            }
        }
        __syncthreads();
    }

    float* Cg = g_C + (size_t)n * BB * NTOT;
    #pragma unroll
    for (int i = 0; i < 2; i++)
        #pragma unroll
        for (int j = 0; j < 2; j++)
            wmma::store_matrix_sync(
                &Cg[(size_t)(m_base + wm * 32 + i * 16) * NTOT + nn_base + wn * 32 + j * 16],
                acc[i][j], NTOT, wmma::mem_row_major);
}

// ---------------- phase 2: bias + threshold + beta-sum + LSTM epilogue ----------------
__global__ void k_combine(const float* __restrict__ cx,
                          const float* __restrict__ bih, const float* __restrict__ bhh,
                          const float* __restrict__ ebih, const float* __restrict__ ebhh,
                          const float* __restrict__ pa3, const float* __restrict__ pa4,
                          const float* __restrict__ pa5, const float* __restrict__ pa6,
                          const float* __restrict__ pa7, const float* __restrict__ pa8,
                          const float* __restrict__ pa9, const float* __restrict__ pa10,
                          const float* __restrict__ pa11,
                          float* __restrict__ out) {
    const int idx = blockIdx.x * blockDim.x + threadIdx.x;  // < BB*1024
    const int b = idx >> 10;
    const int h = idx & 1023;

    const float bmax_ih = g_max[2];
    const float bmax_hh = g_max[3];
    const float beta[4] = {(float)(8.0 / 15.0), (float)(4.0 / 15.0),
                           (float)(2.0 / 15.0), (float)(1.0 / 15.0)};

    float gates[4];
    #pragma unroll
    for (int g = 0; g < 4; g++) {
        const int col = g * 1024 + h;
        float acc = 0.f;
        #pragma unroll
        for (int n = 0; n < NMSB; n++) {
            const size_t base = ((size_t)n * BB + b) * NTOT;
            float o1 = g_C[base + col]        + w_eff_f(bih[n * H4 + col], ebih[n * H4 + col], bmax_ih);
            float o2 = g_C[base + H4 + col]   + w_eff_f(bhh[n * H4 + col], ebhh[n * H4 + col], bmax_hh);
            float outv = ((o1 > 0.5f) ? 1.f : 0.f) + ((o2 > 0.5f) ? 1.f : 0.f);
            acc = acc + beta[n] * outv;
        }
        gates[g] = acc;
    }

    const float A3 = pa3[0],  A4 = pa4[0],  A5 = pa5[0],  A6 = pa6[0];
    const float A7 = pa7[0],  A8 = pa8[0],  A9 = pa9[0],  A10 = pa10[0], A11 = pa11[0];

    const float i_ = gates[0], j_ = gates[1], f_ = gates[2], o_ = gates[3];

    float fg  = quant8(pact_a_f(sig_f(f_), A3), A3);
    float ig  = quant8(pact_a_f(sig_f(i_), A4), A4);
    float act = quant8(pact_a_f(tanhf(j_), A5), A5);
    float og  = quant8(pact_a_f(sig_f(o_), A6), A6);

    float cxv = cx[idx];
    float gc  = quant8(pact_a_f(cxv * fg, A7), A7);
    float ai  = quant8(pact_a_f(ig * act, A8), A8);
    float nc  = quant8(pact_a_f(gc + ai, A9), A9);
    float ac  = quant8(pact_a_f(tanhf(nc), A10), A10);
    float nh  = quant8(pact_a_f(ac * og, A11), A11);

    out[idx] = nh;                // new_h
    out[BB * 1024 + idx] = nc;    // new_c
}

// ---------------- launch ----------------
extern "C" void kernel_launch(void* const* d_in, const int* in_sizes, int n_in,
                              void* d_out, int out_size) {
    const float* input = (const float*)d_in[0];
    // d_in[1] = hx (unused by reference)
    const float* cx    = (const float*)d_in[2];
    const float* wih   = (const float*)d_in[3];
    const float* whh   = (const float*)d_in[4];
    const float* bih   = (const float*)d_in[5];
    const float* bhh   = (const float*)d_in[6];
    const float* ewih  = (const float*)d_in[7];
    const float* ewhh  = (const float*)d_in[8];
    const float* ebih  = (const float*)d_in[9];
    const float* ebhh  = (const float*)d_in[10];
    const float* a1  = (const float*)d_in[11];
    const float* a3  = (const float*)d_in[12];
    const float* a4  = (const float*)d_in[13];
    const float* a5  = (const float*)d_in[14];
    const float* a6  = (const float*)d_in[15];
    const float* a7  = (const float*)d_in[16];
    const float* a8  = (const float*)d_in[17];
    const float* a9  = (const float*)d_in[18];
    const float* a10 = (const float*)d_in[19];
    const float* a11 = (const float*)d_in[20];
    float* out = (float*)d_out;

    const int wsize = NMSB * IND * H4;   // 16,777,216
    const int bsize = NMSB * H4;         // 16,384

    k_init<<<1, 32>>>();
    k_max<<<2048, 256>>>(wih, wsize, 0);
    k_max<<<2048, 256>>>(whh, wsize, 1);
    k_max<<<16, 256>>>(bih, bsize, 2);
    k_max<<<16, 256>>>(bhh, bsize, 3);

    k_bits<<<(BB * IND) / 256, 256>>>(input, a1);

    dim3 gg(NTOT / BN, BB / BM, NMSB);   // (128, 2, 4)
    k_gemm<<<gg, 256>>>(wih, whh, ewih, ewhh);

    k_combine<<<(BB * 1024) / 256, 256>>>(cx, bih, bhh, ebih, ebhh,
                                          a3, a4, a5, a6, a7, a8, a9, a10, a11,
                                          out);
}

// round 7
// speedup vs baseline: 1.4024x; 1.4024x over previous
#include <cuda_runtime.h>
#include <cuda_fp16.h>
#include <mma.h>

using namespace nvcuda;

// Problem constants
#define NMSB 4
#define BB   256            // batch
#define IND  1024           // input dim (= K)
#define H4   4096           // 4*H
#define NTOT 8192           // ih(4096) ++ hh(4096)

// GEMM tiling: full batch per block
#define BM 256
#define BN 64
#define BK 32

// epilogue staging leading dimension (floats). MUST be a multiple of 4
// (16 bytes) per the wmma store_matrix_sync contract.
#define EPL 20

// -------- static device scratch --------
__device__ float         g_max[4];                         // max(wih), max(whh), max(bih), max(bhh)
__device__ float         g_beff[NMSB * NTOT];              // effective biases per (n, col)
__device__ __half        g_x[NMSB * IND * BB];             // bit planes, K-major: [n][k][b]
__device__ unsigned char g_bits[(size_t)NMSB * BB * NTOT]; // thresholded matmul outputs

// -------- exact replicas of reference elementwise ops --------
__device__ __forceinline__ float pact_a_f(float x, float a) {
    float sg = (x > 0.f) ? 1.f : ((x < 0.f) ? -1.f : 0.f);
    float ax = fabsf(x);
    return (sg * 0.5f) * ((ax - fabsf(ax - a)) + a);
}

__device__ __forceinline__ float quant8(float x, float a) {
    float x01 = x / a;
    x01 = fminf(fmaxf(x01, -0.9921875f), 0.9921875f);
    return (rintf(x01 * 128.f) * 0.0078125f) * a;
}

__device__ __forceinline__ float w_eff_f(float w, float eps, float maxw) {
    float c = fminf(fmaxf(w, -0.9921875f), 0.9921875f);
    float q = rintf(c * 128.f) * 0.0078125f;
    return w + ((q - w) + (eps * maxw) * 0.1f);
}

__device__ __forceinline__ float sig_f(float x) {
    return 0.5f * tanhf(0.5f * x) + 0.5f;
}

// ---------------- phase 0a: init maxima ----------------
__global__ void k_init() {
    if (threadIdx.x < 4) g_max[threadIdx.x] = -INFINITY;
}

// ---------------- phase 0b: global max reduction (vectorized) ----------------
__global__ void k_max(const float4* __restrict__ p, int n4, int slot) {
    float m = -INFINITY;
    for (int i = blockIdx.x * blockDim.x + threadIdx.x; i < n4;
         i += gridDim.x * blockDim.x) {
        float4 v = p[i];
        m = fmaxf(m, fmaxf(fmaxf(v.x, v.y), fmaxf(v.z, v.w)));
    }
    #pragma unroll
    for (int o = 16; o; o >>= 1) m = fmaxf(m, __shfl_xor_sync(0xFFFFFFFFu, m, o));
    __shared__ float sm[8];
    if ((threadIdx.x & 31) == 0) sm[threadIdx.x >> 5] = m;
    __syncthreads();
    if (threadIdx.x < 32) {
        float v = (threadIdx.x < (blockDim.x >> 5)) ? sm[threadIdx.x] : -INFINITY;
        #pragma unroll
        for (int o = 16; o; o >>= 1) v = fmaxf(v, __shfl_xor_sync(0xFFFFFFFFu, v, o));
        if (threadIdx.x == 0) {
            if (v >= 0.f) atomicMax((int*)&g_max[slot], __float_as_int(v));
            else          atomicMin((unsigned int*)&g_max[slot], __float_as_uint(v));
        }
    }
}

// ---------------- phase 0c: effective biases ----------------
__global__ void k_bias(const float* __restrict__ bih, const float* __restrict__ bhh,
                       const float* __restrict__ ebih, const float* __restrict__ ebhh) {
    int idx = blockIdx.x * blockDim.x + threadIdx.x;   // < NMSB*NTOT = 32768
    int n = idx >> 13;
    int c = idx & (NTOT - 1);
    int set = c >> 12;
    int cc  = c & (H4 - 1);
    const float* b = set ? bhh : bih;
    const float* e = set ? ebhh : ebih;
    float m = g_max[2 + set];
    g_beff[idx] = w_eff_f(b[n * H4 + cc], e[n * H4 + cc], m);
}

// ---------------- phase 0d: bit planes (K-major layout for coalesced GEMM A) ----
__global__ void k_bits(const float* __restrict__ input, const float* __restrict__ a1p) {
    int idx = blockIdx.x * blockDim.x + threadIdx.x;  // < BB*IND
    int b = idx & (BB - 1);
    int k = idx >> 8;
    float a = a1p[0];
    float x = input[b * IND + k];
    float pact  = pact_a_f(x, a);
    float inp01 = (pact + a) / (a * 2.0f);
    int ri = (int)rintf(15.0f * inp01);   // in [0,15]
    #pragma unroll
    for (int n = 0; n < NMSB; n++) {
        int bit = (ri >> (3 - n)) & 1;
        g_x[n * (IND * BB) + k * BB + b] = __float2half_rn(bit ? 1.f : 0.f);
    }
}

// ---------------- phase 1: pipelined fp16 2-limb GEMM, full-batch tiles --------
// For each n (bit plane) and 64-wide column tile, compute the 256x64 fp32
// matmul block with 2-limb fp16 HMMA, add bias_eff, threshold >0.5, and
// write a uint8 plane. Weights/noise are read exactly once.
__global__ void __launch_bounds__(256)
k_gemm(const float* __restrict__ wih, const float* __restrict__ whh,
       const float* __restrict__ ewih, const float* __restrict__ ewhh) {
    __shared__ __half As[BK][BM + 8];      // col-major A tile (k rows, b cols)
    __shared__ __half Bh[BK][BN + 8];
    __shared__ __half Bl[BK][BN + 8];
    __shared__ float  epi[8][16 * EPL];    // per-warp accumulator staging

    const int n       = blockIdx.z;
    const int nn_base = blockIdx.x * BN;
    const int set     = nn_base >> 12;             // 0: ih, 1: hh
    const float* W = set ? whh : wih;
    const float* E = set ? ewhh : ewih;
    const float maxw = g_max[set];
    const int o_base = nn_base & (H4 - 1);

    const __half* X  = g_x + n * (IND * BB);
    const float*  Wn = W + (size_t)n * IND * H4;
    const float*  En = E + (size_t)n * IND * H4;

    const int tid  = threadIdx.x;
    const int warp = tid >> 5;
    const int lane = tid & 31;
    const int wm   = warp >> 1;   // 0..3 -> 64 rows each
    const int wn   = warp & 1;    // 0..1 -> 32 cols each

    wmma::fragment<wmma::accumulator, 16, 16, 16, float> acc[4][2];
    #pragma unroll
    for (int i = 0; i < 4; i++)
        #pragma unroll
        for (int j = 0; j < 2; j++) wmma::fill_fragment(acc[i][j], 0.f);

    // load assignments
    const int ar   = tid >> 3;           // A: 32 k-rows, 8 threads/row
    const int aseg = (tid & 7) * 32;     // 32 halves = 64B per thread
    const int br   = tid >> 3;           // B: 32 k-rows
    const int bc   = (tid & 7) * 8;      // 8 floats per thread

    uint4  aReg[4];
    float4 wReg[2], eReg[2];

    auto loadT = [&](int k0) {
        const uint4* pa = (const uint4*)(X + (k0 + ar) * BB + aseg);
        aReg[0] = pa[0]; aReg[1] = pa[1]; aReg[2] = pa[2]; aReg[3] = pa[3];
        const float* gw = Wn + (size_t)(k0 + br) * H4 + o_base + bc;
        const float* ge = En + (size_t)(k0 + br) * H4 + o_base + bc;
        wReg[0] = ((const float4*)gw)[0]; wReg[1] = ((const float4*)gw)[1];
        eReg[0] = ((const float4*)ge)[0]; eReg[1] = ((const float4*)ge)[1];
    };

    auto storeT = [&]() {
        uint4* sa = (uint4*)&As[ar][aseg];
        sa[0] = aReg[0]; sa[1] = aReg[1]; sa[2] = aReg[2]; sa[3] = aReg[3];
        float wv[8] = {wReg[0].x, wReg[0].y, wReg[0].z, wReg[0].w,
                       wReg[1].x, wReg[1].y, wReg[1].z, wReg[1].w};
        float ev[8] = {eReg[0].x, eReg[0].y, eReg[0].z, eReg[0].w,
                       eReg[1].x, eReg[1].y, eReg[1].z, eReg[1].w};
        #pragma unroll
        for (int u = 0; u < 8; u++) {
            float weff = w_eff_f(wv[u], ev[u], maxw);
            __half hi  = __float2half_rn(weff);
            float  lo  = weff - __half2float(hi);
            Bh[br][bc + u] = hi;
            Bl[br][bc + u] = __float2half_rn(lo);
        }
    };

    loadT(0);
    for (int k0 = 0; k0 < IND; k0 += BK) {
        storeT();
        __syncthreads();
        if (k0 + BK < IND) loadT(k0 + BK);   // overlap with MMA below

        #pragma unroll
        for (int kk = 0; kk < BK; kk += 16) {
            wmma::fragment<wmma::matrix_a, 16, 16, 16, __half, wmma::col_major> af[4];
            wmma::fragment<wmma::matrix_b, 16, 16, 16, __half, wmma::row_major> bf;
            #pragma unroll
            for (int i = 0; i < 4; i++)
                wmma::load_matrix_sync(af[i], &As[kk][wm * 64 + i * 16], BM + 8);
            #pragma unroll
            for (int j = 0; j < 2; j++) {
                wmma::load_matrix_sync(bf, &Bh[kk][wn * 32 + j * 16], BN + 8);
                #pragma unroll
                for (int i = 0; i < 4; i++) wmma::mma_sync(acc[i][j], af[i], bf, acc[i][j]);
                wmma::load_matrix_sync(bf, &Bl[kk][wn * 32 + j * 16], BN + 8);
                #pragma unroll
                for (int i = 0; i < 4; i++) wmma::mma_sync(acc[i][j], af[i], bf, acc[i][j]);
            }
        }
        __syncthreads();
    }

    // epilogue: bias + threshold -> uint8 planes
    float* ep = epi[warp];
    unsigned char* Bg = g_bits + (size_t)n * BB * NTOT;
    const float* beff = g_beff + n * NTOT;
    const int r  = lane >> 1;
    const int c0 = (lane & 1) * 8;
    #pragma unroll
    for (int i = 0; i < 4; i++) {
        #pragma unroll
        for (int j = 0; j < 2; j++) {
            wmma::store_matrix_sync(ep, acc[i][j], EPL, wmma::mem_row_major);
            __syncwarp();
            int row  = wm * 64 + i * 16 + r;                 // batch index
            int gcol = nn_base + wn * 32 + j * 16 + c0;      // global column
            unsigned long long v = 0;
            #pragma unroll
            for (int u = 0; u < 8; u++) {
                float o = ep[r * EPL + c0 + u] + beff[gcol + u];
                v |= (unsigned long long)(o > 0.5f ? 1 : 0) << (8 * u);
            }
            *(unsigned long long*)(Bg + (size_t)row * NTOT + gcol) = v;
            __syncwarp();
        }
    }
}

// ---------------- phase 2: beta-sum + LSTM epilogue ----------------
__global__ void k_combine(const float* __restrict__ cx,
                          const float* __restrict__ pa3, const float* __restrict__ pa4,
                          const float* __restrict__ pa5, const float* __restrict__ pa6,
                          const float* __restrict__ pa7, const float* __restrict__ pa8,
                          const float* __restrict__ pa9, const float* __restrict__ pa10,
                          const float* __restrict__ pa11,
                          float* __restrict__ out) {
    const int idx = blockIdx.x * blockDim.x + threadIdx.x;  // < BB*1024
    const int b = idx >> 10;
    const int h = idx & 1023;

    const float beta[4] = {(float)(8.0 / 15.0), (float)(4.0 / 15.0),
                           (float)(2.0 / 15.0), (float)(1.0 / 15.0)};

    float gates[4];
    #pragma unroll
    for (int g = 0; g < 4; g++) {
        const int col = g * 1024 + h;
        float acc = 0.f;
        #pragma unroll
        for (int n = 0; n < NMSB; n++) {
            const size_t base = ((size_t)n * BB + b) * NTOT;
            int s = (int)g_bits[base + col] + (int)g_bits[base + H4 + col];
            acc = acc + beta[n] * (float)s;
        }
        gates[g] = acc;
    }

    const float A3 = pa3[0],  A4 = pa4[0],  A5 = pa5[0],  A6 = pa6[0];
    const float A7 = pa7[0],  A8 = pa8[0],  A9 = pa9[0],  A10 = pa10[0], A11 = pa11[0];

    const float i_ = gates[0], j_ = gates[1], f_ = gates[2], o_ = gates[3];

    float fg  = quant8(pact_a_f(sig_f(f_), A3), A3);
    float ig  = quant8(pact_a_f(sig_f(i_), A4), A4);
    float act = quant8(pact_a_f(tanhf(j_), A5), A5);
    float og  = quant8(pact_a_f(sig_f(o_), A6), A6);

    float cxv = cx[idx];
    float gc  = quant8(pact_a_f(cxv * fg, A7), A7);
    float ai  = quant8(pact_a_f(ig * act, A8), A8);
    float nc  = quant8(pact_a_f(gc + ai, A9), A9);
    float ac  = quant8(pact_a_f(tanhf(nc), A10), A10);
    float nh  = quant8(pact_a_f(ac * og, A11), A11);

    out[idx] = nh;                // new_h
    out[BB * 1024 + idx] = nc;    // new_c
}

// ---------------- launch ----------------
extern "C" void kernel_launch(void* const* d_in, const int* in_sizes, int n_in,
                              void* d_out, int out_size) {
    const float* input = (const float*)d_in[0];
    // d_in[1] = hx (unused by reference)
    const float* cx    = (const float*)d_in[2];
    const float* wih   = (const float*)d_in[3];
    const float* whh   = (const float*)d_in[4];
    const float* bih   = (const float*)d_in[5];
    const float* bhh   = (const float*)d_in[6];
    const float* ewih  = (const float*)d_in[7];
    const float* ewhh  = (const float*)d_in[8];
    const float* ebih  = (const float*)d_in[9];
    const float* ebhh  = (const float*)d_in[10];
    const float* a1  = (const float*)d_in[11];
    const float* a3  = (const float*)d_in[12];
    const float* a4  = (const float*)d_in[13];
    const float* a5  = (const float*)d_in[14];
    const float* a6  = (const float*)d_in[15];
    const float* a7  = (const float*)d_in[16];
    const float* a8  = (const float*)d_in[17];
    const float* a9  = (const float*)d_in[18];
    const float* a10 = (const float*)d_in[19];
    const float* a11 = (const float*)d_in[20];
    float* out = (float*)d_out;

    const int w4 = (NMSB * IND * H4) / 4;   // float4 count for weights
    const int b4 = (NMSB * H4) / 4;         // float4 count for biases

    k_init<<<1, 32>>>();
    k_max<<<2048, 256>>>((const float4*)wih, w4, 0);
    k_max<<<2048, 256>>>((const float4*)whh, w4, 1);
    k_max<<<16, 256>>>((const float4*)bih, b4, 2);
    k_max<<<16, 256>>>((const float4*)bhh, b4, 3);

    k_bias<<<(NMSB * NTOT) / 256, 256>>>(bih, bhh, ebih, ebhh);
    k_bits<<<(BB * IND) / 256, 256>>>(input, a1);

    dim3 gg(NTOT / BN, 1, NMSB);   // (128, 1, 4)
    k_gemm<<<gg, 256>>>(wih, whh, ewih, ewhh);

    k_combine<<<(BB * 1024) / 256, 256>>>(cx, a3, a4, a5, a6, a7, a8, a9, a10, a11,
                                          out);
}